// round 8
// baseline (speedup 1.0000x reference)
#include <cuda_runtime.h>
#include <cstdint>
#include <math.h>

#define T_DIRS 384   // num directions (both spaces)
#define N_PTS  384   // num points
#define RES    384   // resolution (thresholds)
#define D1     128
#define D2     32
#define NCELL  387   // cell indices 0..386: cell -1 (below grid) .. 385 (above grid), +1 offset
#define NW     12    // warps per block (384 threads)

// Scratch (no allocations allowed)
__device__ float g_partial[T_DIRS];

// ---------------- Threefry-2x32 (JAX), key = (0, 42) ----------------
__device__ __forceinline__ uint32_t rotl32(uint32_t x, int r) {
    return (x << r) | (x >> (32 - r));
}

__device__ __forceinline__ void threefry2x32_42(uint32_t c0, uint32_t c1,
                                                uint32_t& o0, uint32_t& o1) {
    const uint32_t k0 = 0u, k1 = 42u;
    const uint32_t k2 = 0x1BD11BDAu ^ k0 ^ k1;
    uint32_t x0 = c0 + k0, x1 = c1 + k1;
#define TF_GROUP(r0, r1, r2, r3, ka, kb, inc)                  \
    x0 += x1; x1 = rotl32(x1, r0); x1 ^= x0;                   \
    x0 += x1; x1 = rotl32(x1, r1); x1 ^= x0;                   \
    x0 += x1; x1 = rotl32(x1, r2); x1 ^= x0;                   \
    x0 += x1; x1 = rotl32(x1, r3); x1 ^= x0;                   \
    x0 += (ka); x1 += (kb) + (inc);
    TF_GROUP(13, 15, 26, 6,  k1, k2, 1u)
    TF_GROUP(17, 29, 16, 24, k2, k0, 2u)
    TF_GROUP(13, 15, 26, 6,  k0, k1, 3u)
    TF_GROUP(17, 29, 16, 24, k1, k2, 4u)
    TF_GROUP(13, 15, 26, 6,  k2, k0, 5u)
#undef TF_GROUP
    o0 = x0; o1 = x1;
}

// ---------------- XLA ErfInv (f32, Giles) ----------------
__device__ __forceinline__ float erfinv_xla(float x) {
    float w = -log1pf(-x * x);
    float p;
    if (w < 5.0f) {
        w -= 2.5f;
        p = 2.81022636e-08f;
        p = fmaf(p, w, 3.43273939e-07f);
        p = fmaf(p, w, -3.5233877e-06f);
        p = fmaf(p, w, -4.39150654e-06f);
        p = fmaf(p, w, 0.00021858087f);
        p = fmaf(p, w, -0.00125372503f);
        p = fmaf(p, w, -0.00417768164f);
        p = fmaf(p, w, 0.246640727f);
        p = fmaf(p, w, 1.50140941f);
    } else {
        w = sqrtf(w) - 3.0f;
        p = -0.000200214257f;
        p = fmaf(p, w, 0.000100950558f);
        p = fmaf(p, w, 0.00134934322f);
        p = fmaf(p, w, -0.00367342844f);
        p = fmaf(p, w, 0.00573950773f);
        p = fmaf(p, w, -0.0076224613f);
        p = fmaf(p, w, 0.00943887047f);
        p = fmaf(p, w, 1.00167406f);
        p = fmaf(p, w, 2.83297682f);
    }
    return p * x;
}

// Partitionable threefry layout: counter (0, j), 32-bit draw = y0 ^ y1.
__device__ __forceinline__ float jax_normal_elem(uint32_t j) {
    uint32_t o0, o1;
    threefry2x32_42(0u, j, o0, o1);
    uint32_t bits = o0 ^ o1;
    uint32_t fb = (bits >> 9) | 0x3f800000u;
    float f = __uint_as_float(fb) - 1.0f;          // [0, 1)
    const float lo = -0.99999994f;                  // nextafter(-1, 0)
    float u = f * 2.0f + lo;
    u = fmaxf(lo, u);
    return 1.41421356f * erfinv_xla(u);
}

// ===================== Fused per-direction kernel =====================
// grid = T_DIRS blocks (one per direction t), 384 threads.
// Phase A: generate v1/v2 column t + norms (warp shuffles).
// Phase B: thread n computes nh1[n], nh2[n] (dot with own X row, scale by 1/||v||).
// Phase C: deterministic counting-sort into threshold-grid cells (match_any,
//          no atomics), block scan, scatter.
// Phase D: thread r: ECT(r) = P[r-7] (saturated count) + exact sigmoid over
//          bucketed points in cells [r-8, r+8]; diff^2; block reduce.
__global__ void __launch_bounds__(384) fused_kernel(const float* __restrict__ x1,
                                                    const float* __restrict__ x2) {
    __shared__ float v1s[D1];
    __shared__ float v2s[D2];
    __shared__ float b1[N_PTS], b2[N_PTS];   // bucketed projections
    __shared__ int   wpc[NW * NCELL];        // per-warp per-cell counts
    __shared__ int   hh[NCELL];              // cell totals
    __shared__ int   P1[NCELL + 1], P2[NCELL + 1];  // exclusive prefixes
    __shared__ float red[RES];
    __shared__ float nrm_s[NW];
    __shared__ int   wsum[NW];

    const int tid  = threadIdx.x;
    const int t    = blockIdx.x;
    const int lane = tid & 31;
    const int wid  = tid >> 5;

    // ---------- Phase A: generate direction column t ----------
    float val = 0.0f;
    if (tid < D1) {
        val = jax_normal_elem((uint32_t)(tid * T_DIRS + t));   // v1[(i,t)], [d,T] row-major
        v1s[tid] = val;
    } else if (tid < D1 + D2) {
        int i = tid - D1;
        val = jax_normal_elem((uint32_t)(i * T_DIRS + t));
        v2s[i] = val;
    }
    float sq = val * val;
#pragma unroll
    for (int o = 16; o; o >>= 1) sq += __shfl_xor_sync(0xffffffffu, sq, o);
    if (lane == 0) nrm_s[wid] = sq;
    __syncthreads();
    const float nrm1 = sqrtf(nrm_s[0] + nrm_s[1] + nrm_s[2] + nrm_s[3]);
    const float nrm2 = sqrtf(nrm_s[4]);

    // ---------- Phase B: per-point projections ----------
    float a1 = 0.0f;
    {
        const float4* r1 = reinterpret_cast<const float4*>(x1) + tid * (D1 / 4);
#pragma unroll
        for (int k = 0; k < D1 / 4; ++k) {
            float4 q = __ldg(r1 + k);
            a1 = fmaf(q.x, v1s[4 * k + 0], a1);
            a1 = fmaf(q.y, v1s[4 * k + 1], a1);
            a1 = fmaf(q.z, v1s[4 * k + 2], a1);
            a1 = fmaf(q.w, v1s[4 * k + 3], a1);
        }
    }
    float a2 = 0.0f;
    {
        const float4* r2 = reinterpret_cast<const float4*>(x2) + tid * (D2 / 4);
#pragma unroll
        for (int k = 0; k < D2 / 4; ++k) {
            float4 q = __ldg(r2 + k);
            a2 = fmaf(q.x, v2s[4 * k + 0], a2);
            a2 = fmaf(q.y, v2s[4 * k + 1], a2);
            a2 = fmaf(q.z, v2s[4 * k + 2], a2);
            a2 = fmaf(q.w, v2s[4 * k + 3], a2);
        }
    }
    const float nh1 = a1 / nrm1;
    const float nh2 = a2 / nrm2;

    // ---------- Phase C: counting-sort both spaces ----------
    // cell = floor((nh+1)/step), step = 2/383; idx = clamp(cell,-1,385)+1 in [0,386]
#define ECT_BUCKET_PASS(NH, BKT, PP)                                          \
    {                                                                         \
        for (int i = tid; i < NW * NCELL; i += 384) wpc[i] = 0;               \
        __syncthreads();                                                      \
        int cc  = (int)floorf((NH + 1.0f) * 191.5f);                          \
        int idx = min(max(cc, -1), 385) + 1;                                  \
        unsigned mmask = __match_any_sync(0xffffffffu, idx);                  \
        int leader = __ffs(mmask) - 1;                                        \
        int rank   = __popc(mmask & ((1u << lane) - 1u));                     \
        if (lane == leader) wpc[wid * NCELL + idx] = __popc(mmask);           \
        __syncthreads();                                                      \
        for (int i = tid; i < NCELL; i += 384) {                              \
            int ssum = 0;                                                     \
            _Pragma("unroll")                                                 \
            for (int w = 0; w < NW; ++w) ssum += wpc[w * NCELL + i];          \
            hh[i] = ssum;                                                     \
        }                                                                     \
        __syncthreads();                                                      \
        { /* block exclusive scan of hh[0..386] -> PP[0..387] */              \
            int xv = hh[tid];                                                 \
            int v = xv;                                                       \
            _Pragma("unroll")                                                 \
            for (int o = 1; o < 32; o <<= 1) {                                \
                int y = __shfl_up_sync(0xffffffffu, v, o);                    \
                if (lane >= o) v += y;                                        \
            }                                                                 \
            if (lane == 31) wsum[wid] = v;                                    \
            __syncthreads();                                                  \
            if (wid == 0) {                                                   \
                int w = (lane < NW) ? wsum[lane] : 0;                         \
                _Pragma("unroll")                                             \
                for (int o = 1; o < 16; o <<= 1) {                            \
                    int y = __shfl_up_sync(0xffffffffu, w, o);                \
                    if (lane >= o) w += y;                                    \
                }                                                             \
                if (lane < NW) wsum[lane] = w;                                \
            }                                                                 \
            __syncthreads();                                                  \
            int incl = v + (wid ? wsum[wid - 1] : 0);                         \
            PP[tid] = incl - xv;                                              \
            if (tid == 383) {                                                 \
                int base = incl;                                              \
                PP[384] = base;                                               \
                PP[385] = base + hh[384];                                     \
                PP[386] = PP[385] + hh[385];                                  \
                PP[387] = PP[386] + hh[386];                                  \
            }                                                                 \
        }                                                                     \
        __syncthreads();                                                      \
        { /* deterministic scatter: order = (warp, lane) = point index */     \
            int off = 0;                                                      \
            _Pragma("unroll")                                                 \
            for (int w = 0; w < NW; ++w)                                      \
                if (w < wid) off += wpc[w * NCELL + idx];                     \
            BKT[PP[idx] + off + rank] = NH;                                   \
        }                                                                     \
        __syncthreads();                                                      \
    }

    ECT_BUCKET_PASS(nh1, b1, P1)
    ECT_BUCKET_PASS(nh2, b2, P2)
#undef ECT_BUCKET_PASS

    // ---------- Phase D: per-threshold ECT + loss partial ----------
    const int r = tid;
    const float lin = (float)(-1.0 + 2.0 * (double)r / 383.0);

    float acc1, acc2;
    {
        int loI = max(r - 7, 0), hiI = min(r + 10, NCELL);
        int lo = P1[loI], hi = P1[hiI];
        acc1 = (float)lo;                              // saturated (sigmoid≈1) points
        for (int i = lo; i < hi; ++i) {
            float z = 500.0f * (lin - b1[i]);
            z = fminf(fmaxf(z, -30.0f), 30.0f);
            acc1 += __fdividef(1.0f, 1.0f + __expf(-z));
        }
    }
    {
        int loI = max(r - 7, 0), hiI = min(r + 10, NCELL);
        int lo = P2[loI], hi = P2[hiI];
        acc2 = (float)lo;
        for (int i = lo; i < hi; ++i) {
            float z = 500.0f * (lin - b2[i]);
            z = fminf(fmaxf(z, -30.0f), 30.0f);
            acc2 += __fdividef(1.0f, 1.0f + __expf(-z));
        }
    }

    float d = acc1 - acc2;
    red[r] = d * d;
    __syncthreads();
    if (r < 128) red[r] += red[r + 256];
    __syncthreads();
#pragma unroll
    for (int s = 128; s > 0; s >>= 1) {
        if (r < s) red[r] += red[r + s];
        __syncthreads();
    }
    if (r == 0) g_partial[t] = red[0];
}

// ---------------- Final reduction -> loss ----------------
__global__ void final_kernel(float* __restrict__ out, int out_size) {
    int tid = threadIdx.x;
    __shared__ float sred[T_DIRS];
    sred[tid] = g_partial[tid];
    __syncthreads();
    if (tid < 128) sred[tid] += sred[tid + 256];
    __syncthreads();
#pragma unroll
    for (int s = 128; s > 0; s >>= 1) {
        if (tid < s) sred[tid] += sred[tid + s];
        __syncthreads();
    }
    for (int idx = tid; idx < out_size; idx += blockDim.x)
        if (idx > 0) out[idx] = 0.0f;
    if (tid == 0) out[0] = sred[0] / (float)(RES * T_DIRS);
}

extern "C" void kernel_launch(void* const* d_in, const int* in_sizes, int n_in,
                              void* d_out, int out_size) {
    const float* space1;
    const float* space2;
    if (in_sizes[0] == N_PTS * D1) {
        space1 = (const float*)d_in[0];
        space2 = (const float*)d_in[1];
    } else {
        space1 = (const float*)d_in[1];
        space2 = (const float*)d_in[0];
    }
    float* out = (float*)d_out;

    fused_kernel<<<T_DIRS, 384>>>(space1, space2);
    final_kernel<<<1, T_DIRS>>>(out, out_size);
}

// round 11
// speedup vs baseline: 1.9589x; 1.9589x over previous
#include <cuda_runtime.h>
#include <cstdint>
#include <math.h>

#define T_DIRS 384   // num directions (both spaces)
#define N_PTS  384   // num points
#define RES    384   // resolution (thresholds)
#define D1     128
#define D2     32
#define NCELL  387   // cell idx 0..386: cell -1 (below grid) .. 385 (above), +1 offset
#define NW     12    // warps per block (384 threads)
#define NTILE  16    // points per gemm block

// Scratch (no allocations allowed)
__device__ float g_v1[D1 * T_DIRS];
__device__ float g_v2[D2 * T_DIRS];
__device__ float g_nh1[T_DIRS * N_PTS];   // TRANSPOSED: [t][n]
__device__ float g_nh2[T_DIRS * N_PTS];
__device__ unsigned long long g_acc;
__device__ unsigned int g_done;

// ---------------- Threefry-2x32 (JAX), key = (0, 42) ----------------
__device__ __forceinline__ uint32_t rotl32(uint32_t x, int r) {
    return (x << r) | (x >> (32 - r));
}

__device__ __forceinline__ void threefry2x32_42(uint32_t c0, uint32_t c1,
                                                uint32_t& o0, uint32_t& o1) {
    const uint32_t k0 = 0u, k1 = 42u;
    const uint32_t k2 = 0x1BD11BDAu ^ k0 ^ k1;
    uint32_t x0 = c0 + k0, x1 = c1 + k1;
#define TF_GROUP(r0, r1, r2, r3, ka, kb, inc)                  \
    x0 += x1; x1 = rotl32(x1, r0); x1 ^= x0;                   \
    x0 += x1; x1 = rotl32(x1, r1); x1 ^= x0;                   \
    x0 += x1; x1 = rotl32(x1, r2); x1 ^= x0;                   \
    x0 += x1; x1 = rotl32(x1, r3); x1 ^= x0;                   \
    x0 += (ka); x1 += (kb) + (inc);
    TF_GROUP(13, 15, 26, 6,  k1, k2, 1u)
    TF_GROUP(17, 29, 16, 24, k2, k0, 2u)
    TF_GROUP(13, 15, 26, 6,  k0, k1, 3u)
    TF_GROUP(17, 29, 16, 24, k1, k2, 4u)
    TF_GROUP(13, 15, 26, 6,  k2, k0, 5u)
#undef TF_GROUP
    o0 = x0; o1 = x1;
}

// ---------------- XLA ErfInv (f32, Giles) ----------------
__device__ __forceinline__ float erfinv_xla(float x) {
    float w = -log1pf(-x * x);
    float p;
    if (w < 5.0f) {
        w -= 2.5f;
        p = 2.81022636e-08f;
        p = fmaf(p, w, 3.43273939e-07f);
        p = fmaf(p, w, -3.5233877e-06f);
        p = fmaf(p, w, -4.39150654e-06f);
        p = fmaf(p, w, 0.00021858087f);
        p = fmaf(p, w, -0.00125372503f);
        p = fmaf(p, w, -0.00417768164f);
        p = fmaf(p, w, 0.246640727f);
        p = fmaf(p, w, 1.50140941f);
    } else {
        w = sqrtf(w) - 3.0f;
        p = -0.000200214257f;
        p = fmaf(p, w, 0.000100950558f);
        p = fmaf(p, w, 0.00134934322f);
        p = fmaf(p, w, -0.00367342844f);
        p = fmaf(p, w, 0.00573950773f);
        p = fmaf(p, w, -0.0076224613f);
        p = fmaf(p, w, 0.00943887047f);
        p = fmaf(p, w, 1.00167406f);
        p = fmaf(p, w, 2.83297682f);
    }
    return p * x;
}

// Partitionable threefry layout: counter (0, j), 32-bit draw = y0 ^ y1.
__device__ __forceinline__ float jax_normal_elem(uint32_t j) {
    uint32_t o0, o1;
    threefry2x32_42(0u, j, o0, o1);
    uint32_t bits = o0 ^ o1;
    uint32_t fb = (bits >> 9) | 0x3f800000u;
    float f = __uint_as_float(fb) - 1.0f;          // [0, 1)
    const float lo = -0.99999994f;                  // nextafter(-1, 0)
    float u = f * 2.0f + lo;
    u = fmaxf(lo, u);
    return 1.41421356f * erfinv_xla(u);
}

// ---------------- Kernel 1: generate + normalize direction columns ----------------
// grid (T_DIRS, 2), block 128. y=0 -> v1 (d=128), y=1 -> v2 (d=32).
// Also resets the cross-block accumulator/counter for this graph replay
// (stream order guarantees this completes before the ECT kernel runs).
__global__ void gen_dirs_kernel() {
    if (blockIdx.x == 0 && blockIdx.y == 0 && threadIdx.x == 0) {
        g_acc = 0ULL;
        g_done = 0u;
    }
    int t = blockIdx.x;
    int i = threadIdx.x;
    int which = blockIdx.y;
    int d = which ? D2 : D1;
    float* out = which ? g_v2 : g_v1;

    float val = 0.0f;
    if (i < d) {
        uint32_t j = (uint32_t)(i * T_DIRS + t);   // row-major (d, T)
        val = jax_normal_elem(j);
    }

    __shared__ float sred[128];
    sred[i] = val * val;
    __syncthreads();
    for (int s = 64; s > 0; s >>= 1) {
        if (i < s) sred[i] += sred[i + s];
        __syncthreads();
    }
    float nrm = sqrtf(sred[0]);
    if (i < d) out[i * T_DIRS + t] = val / nrm;
}

// ---------------- Kernel 2: tiled GEMM, nh[t][n] = x[n,:] . v[:,t] ----------------
// grid (T_DIRS/128, N_PTS/NTILE, 2), block 128 (thread = direction t).
// X rows staged in smem (coalesced float4 loads, broadcast reads).
// Output TRANSPOSED [t][n] so the ECT kernel loads coalesced.
__global__ void __launch_bounds__(128) gemm_kernel(const float* __restrict__ x1,
                                                   const float* __restrict__ x2) {
    const int which = blockIdx.z;
    const float* __restrict__ x = which ? x2 : x1;
    const float* __restrict__ v = which ? g_v2 : g_v1;
    float* __restrict__ nh = which ? g_nh2 : g_nh1;
    const int K = which ? D2 : D1;

    const int t  = blockIdx.x * 128 + threadIdx.x;
    const int n0 = blockIdx.y * NTILE;

    __shared__ float xs[NTILE * D1];           // max K
    {
        const float4* src = reinterpret_cast<const float4*>(x + n0 * K);
        float4* dst = reinterpret_cast<float4*>(xs);
        int total = NTILE * K / 4;
        for (int i = threadIdx.x; i < total; i += 128) dst[i] = src[i];
    }
    __syncthreads();

    float acc[NTILE];
#pragma unroll
    for (int i = 0; i < NTILE; ++i) acc[i] = 0.0f;

#pragma unroll 8
    for (int k = 0; k < K; ++k) {
        float vk = v[k * T_DIRS + t];          // coalesced across warp
#pragma unroll
        for (int i = 0; i < NTILE; ++i)
            acc[i] = fmaf(vk, xs[i * K + k], acc[i]);   // smem broadcast
    }

    float4* o = reinterpret_cast<float4*>(nh + t * N_PTS + n0);
#pragma unroll
    for (int i = 0; i < NTILE / 4; ++i)
        o[i] = make_float4(acc[4 * i], acc[4 * i + 1], acc[4 * i + 2], acc[4 * i + 3]);
}

// ---------------- Kernel 3: counting-sort ECT + loss (full reduction) ----------------
// grid T_DIRS (block per direction t), 384 threads (thread = point n, then = threshold r).
__global__ void __launch_bounds__(384) ect_loss_kernel(float* __restrict__ out,
                                                       int out_size) {
    __shared__ float b1[N_PTS], b2[N_PTS];   // bucketed projections
    __shared__ int   wpc[NW * NCELL];        // per-warp per-cell counts
    __shared__ int   hh[NCELL];              // cell totals
    __shared__ int   P1[NCELL + 1], P2[NCELL + 1];
    __shared__ float red[RES];
    __shared__ int   wsum[NW];

    const int tid  = threadIdx.x;
    const int t    = blockIdx.x;
    const int lane = tid & 31;
    const int wid  = tid >> 5;

    const float nh1 = g_nh1[t * N_PTS + tid];   // coalesced
    const float nh2 = g_nh2[t * N_PTS + tid];

    // counting-sort into threshold-grid cells; deterministic (no atomics)
#define ECT_BUCKET_PASS(NH, BKT, PP)                                          \
    {                                                                         \
        for (int i = tid; i < NW * NCELL; i += 384) wpc[i] = 0;               \
        __syncthreads();                                                      \
        int cc  = (int)floorf((NH + 1.0f) * 191.5f);                          \
        int idx = min(max(cc, -1), 385) + 1;                                  \
        unsigned mmask = __match_any_sync(0xffffffffu, idx);                  \
        int leader = __ffs(mmask) - 1;                                        \
        int rank   = __popc(mmask & ((1u << lane) - 1u));                     \
        if (lane == leader) wpc[wid * NCELL + idx] = __popc(mmask);           \
        __syncthreads();                                                      \
        for (int i = tid; i < NCELL; i += 384) {                              \
            int ssum = 0;                                                     \
            _Pragma("unroll")                                                 \
            for (int w = 0; w < NW; ++w) ssum += wpc[w * NCELL + i];          \
            hh[i] = ssum;                                                     \
        }                                                                     \
        __syncthreads();                                                      \
        {                                                                     \
            int xv = hh[tid];                                                 \
            int v = xv;                                                       \
            _Pragma("unroll")                                                 \
            for (int o = 1; o < 32; o <<= 1) {                                \
                int y = __shfl_up_sync(0xffffffffu, v, o);                    \
                if (lane >= o) v += y;                                        \
            }                                                                 \
            if (lane == 31) wsum[wid] = v;                                    \
            __syncthreads();                                                  \
            if (wid == 0) {                                                   \
                int w = (lane < NW) ? wsum[lane] : 0;                         \
                _Pragma("unroll")                                             \
                for (int o = 1; o < 16; o <<= 1) {                            \
                    int y = __shfl_up_sync(0xffffffffu, w, o);                \
                    if (lane >= o) w += y;                                    \
                }                                                             \
                if (lane < NW) wsum[lane] = w;                                \
            }                                                                 \
            __syncthreads();                                                  \
            int incl = v + (wid ? wsum[wid - 1] : 0);                         \
            PP[tid] = incl - xv;                                              \
            if (tid == 383) {                                                 \
                int base = incl;                                              \
                PP[384] = base;                                               \
                PP[385] = base + hh[384];                                     \
                PP[386] = PP[385] + hh[385];                                  \
                PP[387] = PP[386] + hh[386];                                  \
            }                                                                 \
        }                                                                     \
        __syncthreads();                                                      \
        {                                                                     \
            int off = 0;                                                      \
            _Pragma("unroll")                                                 \
            for (int w = 0; w < NW; ++w)                                      \
                if (w < wid) off += wpc[w * NCELL + idx];                     \
            BKT[PP[idx] + off + rank] = NH;                                   \
        }                                                                     \
        __syncthreads();                                                      \
    }

    ECT_BUCKET_PASS(nh1, b1, P1)
    ECT_BUCKET_PASS(nh2, b2, P2)
#undef ECT_BUCKET_PASS

    // per-threshold ECT + squared diff
    const int r = tid;
    const float lin = (float)(-1.0 + 2.0 * (double)r / 383.0);

    float acc1, acc2;
    {
        int loI = max(r - 7, 0), hiI = min(r + 10, NCELL);
        int lo = P1[loI], hi = P1[hiI];
        acc1 = (float)lo;
        for (int i = lo; i < hi; ++i) {
            float z = 500.0f * (lin - b1[i]);
            z = fminf(fmaxf(z, -30.0f), 30.0f);
            acc1 += __fdividef(1.0f, 1.0f + __expf(-z));
        }
    }
    {
        int loI = max(r - 7, 0), hiI = min(r + 10, NCELL);
        int lo = P2[loI], hi = P2[hiI];
        acc2 = (float)lo;
        for (int i = lo; i < hi; ++i) {
            float z = 500.0f * (lin - b2[i]);
            z = fminf(fmaxf(z, -30.0f), 30.0f);
            acc2 += __fdividef(1.0f, 1.0f + __expf(-z));
        }
    }

    float d = acc1 - acc2;
    red[r] = d * d;
    __syncthreads();
    if (r < 128) red[r] += red[r + 256];
    __syncthreads();
#pragma unroll
    for (int s = 128; s > 0; s >>= 1) {
        if (r < s) red[r] += red[r + s];
        __syncthreads();
    }

    // deterministic cross-block reduction: fixed-point (2^-32) integer atomics
    if (r == 0) {
        unsigned long long q =
            (unsigned long long)llrint((double)red[0] * 4294967296.0);
        atomicAdd(&g_acc, q);
        __threadfence();
        unsigned int done = atomicAdd(&g_done, 1u);
        if (done == gridDim.x - 1) {
            unsigned long long tot = atomicAdd(&g_acc, 0ULL);
            double loss = ((double)tot / 4294967296.0) / (double)(RES * T_DIRS);
            out[0] = (float)loss;
            for (int i = 1; i < out_size; ++i) out[i] = 0.0f;
        }
    }
}

extern "C" void kernel_launch(void* const* d_in, const int* in_sizes, int n_in,
                              void* d_out, int out_size) {
    const float* space1;
    const float* space2;
    if (in_sizes[0] == N_PTS * D1) {
        space1 = (const float*)d_in[0];
        space2 = (const float*)d_in[1];
    } else {
        space1 = (const float*)d_in[1];
        space2 = (const float*)d_in[0];
    }
    float* out = (float*)d_out;

    gen_dirs_kernel<<<dim3(T_DIRS, 2), 128>>>();
    gemm_kernel<<<dim3(T_DIRS / 128, N_PTS / NTILE, 2), 128>>>(space1, space2);
    ect_loss_kernel<<<T_DIRS, 384>>>(out, out_size);
}